// round 11
// baseline (speedup 1.0000x reference)
#include <cuda_runtime.h>

#define RFN 512
#define TN  32
#define KN  32
#define LN  2048
#define LQ  512              // L per quarter (l-split x4)
#define BK  32
#define NTILE (LQ / BK)      // 16
#define STAGES 2
#define NPAIR 256
#define NCTA (NPAIR * 4)     // 1024: pair = bid>>2, quarter = bid&3

__device__ unsigned long long g_part[NCTA][64][32];  // [cta][accidx][lane] 16.8 MB
__device__ int g_cnt[NPAIR];                         // per-pair tickets (reset after use)

// Packed double fp32 FMA / ADD (Blackwell f32x2) — PTX only.
__device__ __forceinline__ unsigned long long ffma2(unsigned long long a,
                                                    unsigned long long b,
                                                    unsigned long long c) {
    unsigned long long d;
    asm volatile("fma.rn.f32x2 %0, %1, %2, %3;" : "=l"(d) : "l"(a), "l"(b), "l"(c));
    return d;
}
__device__ __forceinline__ unsigned long long add2f(unsigned long long a,
                                                    unsigned long long b) {
    unsigned long long d;
    asm volatile("add.rn.f32x2 %0, %1, %2;" : "=l"(d) : "l"(a), "l"(b));
    return d;
}

__device__ __forceinline__ void cp_async16(unsigned dst, const float* src) {
    asm volatile("cp.async.cg.shared.global [%0], [%1], 16;" :: "r"(dst), "l"(src) : "memory");
}

// grid = 1024: pair = bid>>2 (branches 2p,2p+1), q = bid&3 (l quarter)
// block = 32: lanes 0-15 -> branch 2p, lanes 16-31 -> branch 2p+1; 8t x 8k per lane.
__global__ __launch_bounds__(32)
void spyke_gemm(const float* __restrict__ rec,   // (T=32, C=1, RF=512, L=2048)
                const float* __restrict__ Wt,    // (RF=512, K=32, C=1, L=2048)
                float* __restrict__ out)         // (T, 1, K, RF)
{
    // [stage][branch][row][l], 16B-chunk swizzled: col = c4 ^ (row&7) ^ (branch<<2)
    __shared__ __align__(16) float As[STAGES][2][TN][BK];   // 16 KB
    __shared__ __align__(16) float Bs[STAGES][2][KN][BK];   // 16 KB

    const int lane = threadIdx.x;
    const int bsel = lane >> 4;        // branch within pair (compute role)
    const int l16  = lane & 15;
    const int rg   = l16 >> 2;         // 0..3 -> t rows {rg+4j, j=0..7}
    const int cg   = l16 & 3;          // 0..3 -> k cols {cg+4c, c=0..7}
    const int pair = blockIdx.x >> 2;
    const int lb   = (blockIdx.x & 3) * LQ;

    const unsigned sA = (unsigned)__cvta_generic_to_shared(&As[0][0][0][0]);
    const unsigned sB = (unsigned)__cvta_generic_to_shared(&Bs[0][0][0][0]);

    // ---- fill addressing (loader role): r0 = lane>>3, c4 = lane&7 ----
    const int r0 = lane >> 3;          // 0..3
    const int c4 = lane & 7;
    const float* pA = rec + ((size_t)r0 * RFN + (size_t)pair * 2) * LN + c4 * 4 + lb;
    const float* pB = Wt + ((size_t)pair * 2 * KN + r0) * LN + c4 * 4 + lb;
    const unsigned colE = (unsigned)((c4 ^ r0) * 16);
    const unsigned saE = sA + (unsigned)(r0 * 128) + colE;
    const unsigned saO = sA + (unsigned)(r0 * 128) + (colE ^ 64u);
    const unsigned sbE = sB + (unsigned)(r0 * 128) + colE;
    const unsigned sbO = sB + (unsigned)(r0 * 128) + (colE ^ 64u);

    unsigned long long acc[8][8];
#pragma unroll
    for (int j = 0; j < 8; j++)
#pragma unroll
        for (int c = 0; c < 8; c++) acc[j][c] = 0ull;

    // one tile = 512 16B chunks per array; i encodes (wb = i>>3, iL = i&7):
    // row = r0 + 4*iL, parity b = (iL&1)^wb flips swizzle bit via ^64.
    auto fill = [&](int s, int dl) {
#pragma unroll
        for (int i = 0; i < 16; i++) {
            const int wb = i >> 3, iL = i & 7;
            const int b = (iL & 1) ^ wb;
            const unsigned smoff = (unsigned)(s * 8192 + wb * 4096 + iL * 512);
            cp_async16((b ? saO : saE) + smoff,
                       pA + dl + (size_t)(4 * iL) * (RFN * LN) + (size_t)wb * LN);
            cp_async16((b ? sbO : sbE) + smoff,
                       pB + dl + ((size_t)wb * KN + 4 * iL) * LN);
        }
        asm volatile("cp.async.commit_group;" ::: "memory");
    };

    fill(0, 0);

    for (int ti = 0; ti < NTILE; ti++) {
        if (ti + 1 < NTILE) {
            fill((ti + 1) & 1, (ti + 1) * BK);
            asm volatile("cp.async.wait_group 1;" ::: "memory");
        } else {
            asm volatile("cp.async.wait_group 0;" ::: "memory");
        }
        __syncwarp();

        const int buf = ti & 1;
#pragma unroll
        for (int lc4 = 0; lc4 < BK / 4; lc4++) {
            asm volatile("" ::: "memory");   // forbid hoisting next lc4's LDS
            ulonglong2 bv[8];
#pragma unroll
            for (int c = 0; c < 8; c++) {
                const int row = cg + 4 * c;
                bv[c] = *(const ulonglong2*)
                    &Bs[buf][bsel][row][(lc4 ^ (row & 7) ^ (bsel << 2)) * 4];
            }
#pragma unroll
            for (int jh = 0; jh < 2; jh++) {
                ulonglong2 av[4];
#pragma unroll
                for (int j = 0; j < 4; j++) {
                    const int row = rg + 4 * (jh * 4 + j);
                    av[j] = *(const ulonglong2*)
                        &As[buf][bsel][row][(lc4 ^ (row & 7) ^ (bsel << 2)) * 4];
                }
#pragma unroll
                for (int j = 0; j < 4; j++)
#pragma unroll
                    for (int c = 0; c < 8; c++) {
                        acc[jh * 4 + j][c] = ffma2(av[j].x, bv[c].x, acc[jh * 4 + j][c]);
                        acc[jh * 4 + j][c] = ffma2(av[j].y, bv[c].y, acc[jh * 4 + j][c]);
                    }
            }
        }
    }

    // ---- store packed partials (coalesced: 32 lanes x 8B per accidx) ----
    {
        unsigned long long* dst = &g_part[blockIdx.x][0][0];
#pragma unroll
        for (int j = 0; j < 8; j++)
#pragma unroll
            for (int c = 0; c < 8; c++)
                dst[(j * 8 + c) * 32 + lane] = acc[j][c];
    }

    __threadfence();
    int old = 0;
    if (lane == 0) old = atomicAdd(&g_cnt[pair], 1);
    old = __shfl_sync(0xffffffffu, old, 0);
    if (old != 3) return;
    __threadfence();   // acquire: all quarters' partials visible

    // ---- finisher: combine quarters, threshold, kWTA, output (lane = k) ----
    float* thr_sh = (float*)&As[0][0][0][0];     // dead tile smem: [t][33]

    for (int bs = 0; bs < 2; bs++) {
        const int r = pair * 2 + bs;
        float th[TN];
        int cnt = 0;
#pragma unroll
        for (int t = 0; t < TN; t++) {
            const int accidx = (t >> 2) * 8 + (lane >> 2);
            const int glane  = bs * 16 + (t & 3) * 4 + (lane & 3);
            unsigned long long p0 = g_part[pair * 4 + 0][accidx][glane];
            unsigned long long p1 = g_part[pair * 4 + 1][accidx][glane];
            unsigned long long p2 = g_part[pair * 4 + 2][accidx][glane];
            unsigned long long p3 = g_part[pair * 4 + 3][accidx][glane];
            unsigned long long s4 = add2f(add2f(p0, p1), add2f(p2, p3));
            float lo = __uint_as_float((unsigned)(s4 & 0xffffffffull));
            float hi = __uint_as_float((unsigned)(s4 >> 32));
            float pot = lo + hi;
            float tv = (pot > 20.0f) ? pot : 0.0f;
            th[t] = tv;
            cnt += (tv > 0.0f) ? 1 : 0;
            thr_sh[t * 33 + lane] = tv;          // for dynamic 'first' lookup
        }
        int first = 32 - cnt;
        if (first > 31) first = 31;              // cnt==0 -> 31 ; cnt>=1 -> 0..31
        float vals = thr_sh[first * 33 + lane];
        float vk = (cnt > 0) ? vals : 0.0f;
        float vmax = vk;
#pragma unroll
        for (int o = 16; o > 0; o >>= 1) {
            float ov = __shfl_xor_sync(0xffffffffu, vmax, o);
            vmax = (ov > vmax) ? ov : vmax;
        }
        const float v = vmax * 32.0f;
        const float total = (float)cnt * (vals + v);

        float cur = total;
        bool win = false;
#pragma unroll
        for (int it = 0; it < 4; it++) {
            float bvv = cur;
            int bi = lane;
#pragma unroll
            for (int o = 16; o > 0; o >>= 1) {
                float ov = __shfl_xor_sync(0xffffffffu, bvv, o);
                int   oi = __shfl_xor_sync(0xffffffffu, bi, o);
                if (ov > bvv || (ov == bvv && oi < bi)) { bvv = ov; bi = oi; }
            }
            if (lane == bi) {
                if (cur > 0.0f) win = true;      // valid = top_val != 0
                cur = -1.0f;                     // exclude from later rounds
            }
        }

#pragma unroll
        for (int t = 0; t < TN; t++) {
            out[(size_t)t * (KN * RFN) + (size_t)lane * RFN + r] =
                (win && th[t] > 0.0f) ? 1.0f : 0.0f;
        }
    }

    if (lane == 0) g_cnt[pair] = 0;              // reset for next graph replay
}

extern "C" void kernel_launch(void* const* d_in, const int* in_sizes, int n_in,
                              void* d_out, int out_size) {
    const float* rec = (const float*)d_in[0];   // rec_field (32,1,512,2048)
    const float* Wt  = (const float*)d_in[1];   // W (512,32,1,2048)
    // d_in[2] = reward — unused by the reference output
    float* out = (float*)d_out;                 // (32,1,32,512)
    spyke_gemm<<<NCTA, 32>>>(rec, Wt, out);
}